// round 8
// baseline (speedup 1.0000x reference)
#include <cuda_runtime.h>
#include <stdint.h>

#define NROWS 65536
#define KDIM  2048
#define BM 128
#define BN 64
#define BK 32
#define NKT (KDIM / BK)   // 64
#define NT  256

// ---------------- device scratch ----------------
__device__ int g_cnt[4];
__device__ int g_perm[4][NROWS];          // 1 MB
__device__ float g_W1tf[KDIM * 384];      // 3 MB: sc|st|wm|ch (K-major [k][n]), tf32
__device__ float g_h1[25165824];          // 96 MB: per-expert compact h1

#define W1OFF_SC 0
#define W1OFF_ST (KDIM * 64)
#define W1OFF_WM (KDIM * 128)
#define W1OFF_CH (KDIM * 256)
// h1 base offsets (floats): sc(64/row), st(64/row), wm(128/row), ch(128/row)
#define H1OFF_SC 0
#define H1OFF_ST (NROWS * 64)
#define H1OFF_WM (NROWS * 128)
#define H1OFF_CH (NROWS * 256)

// ---------------- helpers ----------------
__device__ __forceinline__ void cp16(float* dst, const float* src) {
    uint32_t d = (uint32_t)__cvta_generic_to_shared(dst);
    asm volatile("cp.async.ca.shared.global [%0], [%1], 16;\n" :: "r"(d), "l"(src));
}
__device__ __forceinline__ uint32_t f2tf(float x) {
    uint32_t u; asm("cvt.rna.tf32.f32 %0, %1;" : "=r"(u) : "f"(x)); return u;
}

// ---------------- prep: tf32-round W1 (K-major concat) ----------------
__global__ void prep_kernel(const float* __restrict__ W1_sc, const float* __restrict__ W1_st,
                            const float* __restrict__ W1_wm, const float* __restrict__ W1_ch) {
    const int T = KDIM * 384;
    for (int i = blockIdx.x * blockDim.x + threadIdx.x; i < T;
         i += gridDim.x * blockDim.x) {
        float v;
        if (i < W1OFF_ST)      v = W1_sc[i];
        else if (i < W1OFF_WM) v = W1_st[i - W1OFF_ST];
        else if (i < W1OFF_CH) v = W1_wm[i - W1OFF_WM];
        else                   v = W1_ch[i - W1OFF_CH];
        g_W1tf[i] = __uint_as_float(f2tf(v));
    }
}

// ---------------- bucket kernels ----------------
__global__ void zero_cnt_kernel() {
    if (threadIdx.x < 4) g_cnt[threadIdx.x] = 0;
}

__global__ void bucket_kernel(const int* __restrict__ labels, float* __restrict__ out) {
    int r = blockIdx.x * blockDim.x + threadIdx.x;
    if (r >= NROWS) return;
    int lab = labels[r];
    bool valid = (lab >= 0) && (lab <= 3);
    if (!valid) { out[r] = 0.f; lab = -1; }
    int lane = threadIdx.x & 31;
#pragma unroll
    for (int l = 0; l < 4; l++) {
        unsigned mask = __ballot_sync(0xffffffffu, lab == l);
        if (lab == l) {
            int leader = __ffs(mask) - 1;
            int myrank = __popc(mask & ((1u << lane) - 1));
            int basep = 0;
            if (lane == leader) basep = atomicAdd(&g_cnt[l], __popc(mask));
            basep = __shfl_sync(mask, basep, leader);
            g_perm[l][basep + myrank] = r;
        }
    }
}

// ---------------- GEMM kernel: uniform 128x64x2048 tiles ----------------
// grid: 512 chunks x 6 units. unit -> (expert, nhalf):
//   0:(sc,0) 1:(st,0) 2:(wm,0) 3:(wm,1) 4:(ch,0) 5:(ch,1)
// h1[e] compact: row = bucket position, stride = He.
__constant__ int c_unit_e[6]  = {0, 1, 2, 2, 3, 3};
__constant__ int c_unit_nh[6] = {0, 0, 0, 1, 0, 1};

#define ABUF 4096    // 128x32 floats
#define BBUF 2048    // 32x64 floats
#define OFF_B (3 * ABUF)
#define OFF_TAIL (OFF_B + 3 * BBUF)
#define GEMM_SMEM_FLOATS (OFF_TAIL + 128)

__global__ __launch_bounds__(NT, 2) void gemm_kernel(
    const float* __restrict__ X,
    const float* __restrict__ b1_sc, const float* __restrict__ b1_st,
    const float* __restrict__ b1_wm, const float* __restrict__ b1_ch)
{
    int unit  = blockIdx.x % 6;
    int chunk = blockIdx.x / 6;
    int e  = c_unit_e[unit];
    int nh = c_unit_nh[unit];

    int count = g_cnt[e];
    int base = chunk * BM;
    if (base >= count) return;

    int Hw = (e < 2) ? 64 : 128;                 // W1/h1 row stride
    const float* W1 = g_W1tf +
        (e == 0 ? W1OFF_SC : e == 1 ? W1OFF_ST : e == 2 ? W1OFF_WM : W1OFF_CH) + nh * 64;
    const float* b1 = (e == 0 ? b1_sc : e == 1 ? b1_st : e == 2 ? b1_wm : b1_ch) + nh * 64;
    float* h1g = g_h1 +
        (e == 0 ? H1OFF_SC : e == 1 ? H1OFF_ST : e == 2 ? (size_t)H1OFF_WM
                                               : (size_t)H1OFF_CH) +
        (size_t)base * Hw + nh * 64;
    const int* perm = g_perm[e];

    extern __shared__ float smem[];
    float* As   = smem;
    float* Bs   = smem + OFF_B;
    int*   sRow = (int*)(smem + OFF_TAIL);

    int tid = threadIdx.x, lane = tid & 31, warp = tid >> 5;
    int wm = warp & 3;        // 32 rows each
    int wn = warp >> 2;       // 0..1, 32 cols each

    if (tid < BM) {
        int idx = base + tid;
        if (idx >= count) idx = count - 1;
        sRow[tid] = perm[idx];
    }
    __syncthreads();

    int rid[4];
#pragma unroll
    for (int it = 0; it < 4; it++) rid[it] = sRow[(tid + it * NT) >> 3];

    float acc[2][4][4];
#pragma unroll
    for (int i = 0; i < 2; i++)
#pragma unroll
        for (int j = 0; j < 4; j++)
#pragma unroll
            for (int r = 0; r < 4; r++) acc[i][j][r] = 0.f;

    auto loadA = [&](int buf, int kt) {
        float* dst = As + buf * ABUF;
#pragma unroll
        for (int it = 0; it < 4; it++) {
            int slot = tid + it * NT;
            int r  = slot >> 3;
            int c4 = (slot & 7) << 2;
            int pc = c4 ^ ((r & 7) << 2);
            cp16(dst + r * BK + pc, X + (size_t)rid[it] * KDIM + kt * BK + c4);
        }
    };
    auto loadB = [&](int buf, int kt) {
        float* dst = Bs + buf * BBUF;
        const float* src = W1 + (size_t)kt * BK * Hw;
#pragma unroll
        for (int it = 0; it < 2; it++) {
            int slot = tid + it * NT;
            int r  = slot >> 4;               // k row 0..31
            int c4 = (slot & 15) << 2;        // n col (floats)
            int pc = c4 ^ ((r & 3) << 3);
            cp16(dst + r * BN + pc, src + r * Hw + c4);
        }
    };

    loadA(0, 0); loadB(0, 0);
    asm volatile("cp.async.commit_group;\n");
    loadA(1, 1); loadB(1, 1);
    asm volatile("cp.async.commit_group;\n");

    for (int kt = 0; kt < NKT; kt++) {
        int buf = kt % 3;
        if (kt + 2 < NKT) {
            int nb = (kt + 2) % 3;
            loadA(nb, kt + 2);
            loadB(nb, kt + 2);
            asm volatile("cp.async.commit_group;\n");
            asm volatile("cp.async.wait_group 2;\n");
        } else if (kt + 1 < NKT) {
            asm volatile("cp.async.wait_group 1;\n");
        } else {
            asm volatile("cp.async.wait_group 0;\n");
        }
        __syncthreads();

        const float* A0 = As + buf * ABUF;
        const float* B0 = Bs + buf * BBUF;

#pragma unroll
        for (int ks = 0; ks < 4; ks++) {
            uint32_t afr[2][4];
#pragma unroll
            for (int i = 0; i < 2; i++) {
                int row  = wm * 32 + i * 16 + (lane >> 2);
                int row8 = row + 8;
                int c0 = ks * 8 + (lane & 3);
                int c1 = c0 + 4;
                afr[i][0] = f2tf(A0[row  * BK + (c0 ^ ((row  & 7) << 2))]);
                afr[i][1] = f2tf(A0[row8 * BK + (c0 ^ ((row8 & 7) << 2))]);
                afr[i][2] = f2tf(A0[row  * BK + (c1 ^ ((row  & 7) << 2))]);
                afr[i][3] = f2tf(A0[row8 * BK + (c1 ^ ((row8 & 7) << 2))]);
            }
            uint32_t bfr[4][2];
#pragma unroll
            for (int j = 0; j < 4; j++) {
                int n  = wn * 32 + j * 8 + (lane >> 2);
                int k0 = ks * 8 + (lane & 3);
                int k1 = k0 + 4;
                bfr[j][0] = __float_as_uint(B0[k0 * BN + (n ^ ((k0 & 3) << 3))]);
                bfr[j][1] = __float_as_uint(B0[k1 * BN + (n ^ ((k1 & 3) << 3))]);
            }
#pragma unroll
            for (int i = 0; i < 2; i++)
#pragma unroll
                for (int j = 0; j < 4; j++) {
                    asm volatile(
                        "mma.sync.aligned.m16n8k8.row.col.f32.tf32.tf32.f32 "
                        "{%0,%1,%2,%3}, {%4,%5,%6,%7}, {%8,%9}, {%0,%1,%2,%3};\n"
                        : "+f"(acc[i][j][0]), "+f"(acc[i][j][1]),
                          "+f"(acc[i][j][2]), "+f"(acc[i][j][3])
                        : "r"(afr[i][0]), "r"(afr[i][1]), "r"(afr[i][2]), "r"(afr[i][3]),
                          "r"(bfr[j][0]), "r"(bfr[j][1]));
                }
        }
        __syncthreads();
    }

    // ---- epilogue: +b1, relu, store h1 (fp32, compact, stride Hw) ----
#pragma unroll
    for (int i = 0; i < 2; i++) {
        int row0 = wm * 32 + i * 16 + (lane >> 2);
        int row1 = row0 + 8;
#pragma unroll
        for (int j = 0; j < 4; j++) {
            int col = wn * 32 + j * 8 + 2 * (lane & 3);
            float bv0 = __ldg(b1 + col), bv1 = __ldg(b1 + col + 1);
            float2 v0 = make_float2(fmaxf(acc[i][j][0] + bv0, 0.f),
                                    fmaxf(acc[i][j][1] + bv1, 0.f));
            float2 v1 = make_float2(fmaxf(acc[i][j][2] + bv0, 0.f),
                                    fmaxf(acc[i][j][3] + bv1, 0.f));
            *(float2*)&h1g[(size_t)row0 * Hw + col] = v0;
            *(float2*)&h1g[(size_t)row1 * Hw + col] = v1;
        }
    }
}

// ---------------- stage 2+3: fp32 tail (layers 2,3 for selected expert) ----------------
// smem: W2 sc@0(2048) st@2048 wm@4096(8192) ch@12288(8192)
//       W3 @20480/20512/20544/20608 ; b2 @20672/20704/20736/20800 ; b3 @20864(4)
#define S2_FLOATS 20868

__global__ __launch_bounds__(256) void stage2_kernel(
    const float* __restrict__ W2_sc, const float* __restrict__ b2_sc,
    const float* __restrict__ W3_sc, const float* __restrict__ b3_sc,
    const float* __restrict__ W2_st, const float* __restrict__ b2_st,
    const float* __restrict__ W3_st, const float* __restrict__ b3_st,
    const float* __restrict__ W2_wm, const float* __restrict__ b2_wm,
    const float* __restrict__ W3_wm, const float* __restrict__ b3_wm,
    const float* __restrict__ W2_ch, const float* __restrict__ b2_ch,
    const float* __restrict__ W3_ch, const float* __restrict__ b3_ch,
    float* __restrict__ out)
{
    extern __shared__ float s[];
    int tid = threadIdx.x;

    for (int i = tid; i < 2048; i += 256) s[i]         = W2_sc[i];
    for (int i = tid; i < 2048; i += 256) s[2048 + i]  = W2_st[i];
    for (int i = tid; i < 8192; i += 256) s[4096 + i]  = W2_wm[i];
    for (int i = tid; i < 8192; i += 256) s[12288 + i] = W2_ch[i];
    if (tid < 32) s[20480 + tid] = W3_sc[tid];
    if (tid < 32) s[20512 + tid] = W3_st[tid];
    if (tid < 64) s[20544 + tid] = W3_wm[tid];
    if (tid < 64) s[20608 + tid] = W3_ch[tid];
    if (tid < 32) s[20672 + tid] = b2_sc[tid];
    if (tid < 32) s[20704 + tid] = b2_st[tid];
    if (tid < 64) s[20736 + tid] = b2_wm[tid];
    if (tid < 64) s[20800 + tid] = b2_ch[tid];
    if (tid == 0) { s[20864] = b3_sc[0]; s[20865] = b3_st[0];
                    s[20866] = b3_wm[0]; s[20867] = b3_ch[0]; }
    __syncthreads();

    int lane = tid & 31, wid = tid >> 5;
    int c0 = g_cnt[0], c1 = g_cnt[1], c2 = g_cnt[2], c3 = g_cnt[3];
    int p01 = c0 + c1, p012 = p01 + c2, total = p012 + c3;

    const size_t h1o[4] = {H1OFF_SC, H1OFF_ST, (size_t)H1OFF_WM, (size_t)H1OFF_CH};
    const int hs[4]  = {64, 64, 128, 128};
    const int h2s[4] = {32, 32, 64, 64};
    const int w2o[4] = {0, 2048, 4096, 12288};
    const int w3o[4] = {20480, 20512, 20544, 20608};
    const int b2o[4] = {20672, 20704, 20736, 20800};

    for (int pos = blockIdx.x * 8 + wid; pos < total; pos += gridDim.x * 8) {
        int e, local;
        if (pos < c0)        { e = 0; local = pos; }
        else if (pos < p01)  { e = 1; local = pos - c0; }
        else if (pos < p012) { e = 2; local = pos - p01; }
        else                 { e = 3; local = pos - p012; }

        int h  = hs[e];
        int h2 = h2s[e];
        const float* yrow = g_h1 + h1o[e] + (size_t)local * h;

        float y0 = yrow[lane];
        float y1 = yrow[32 + lane];
        float y2 = (h == 128) ? yrow[64 + lane] : 0.f;
        float y3 = (h == 128) ? yrow[96 + lane] : 0.f;

        float acc0 = s[b2o[e] + lane];
        float acc1 = (h2 == 64) ? s[b2o[e] + 32 + lane] : 0.f;
        const float* w2 = s + w2o[e];

#pragma unroll
        for (int c = 0; c < 4; c++) {
            if (c >= (h >> 5)) break;
            float yc = (c == 0) ? y0 : (c == 1) ? y1 : (c == 2) ? y2 : y3;
#pragma unroll
            for (int ii = 0; ii < 32; ii++) {
                float v = __shfl_sync(0xffffffffu, yc, ii);
                int i = c * 32 + ii;
                acc0 += v * w2[i * h2 + lane];
                if (h2 == 64) acc1 += v * w2[i * h2 + 32 + lane];
            }
        }
        acc0 = fmaxf(acc0, 0.f);
        acc1 = fmaxf(acc1, 0.f);

        float p = acc0 * s[w3o[e] + lane];
        if (h2 == 64) p += acc1 * s[w3o[e] + 32 + lane];
#pragma unroll
        for (int off = 16; off; off >>= 1)
            p += __shfl_xor_sync(0xffffffffu, p, off);

        if (lane == 0) out[g_perm[e][local]] = p + s[20864 + e];
    }
}

// ---------------- launch ----------------
extern "C" void kernel_launch(void* const* d_in, const int* in_sizes, int n_in,
                              void* d_out, int out_size) {
    const float* x      = (const float*)d_in[0];
    const int*   labels = (const int*)d_in[1];
    const float* W1_sc = (const float*)d_in[2],  *b1_sc = (const float*)d_in[3];
    const float* W2_sc = (const float*)d_in[4],  *b2_sc = (const float*)d_in[5];
    const float* W3_sc = (const float*)d_in[6],  *b3_sc = (const float*)d_in[7];
    const float* W1_st = (const float*)d_in[8],  *b1_st = (const float*)d_in[9];
    const float* W2_st = (const float*)d_in[10], *b2_st = (const float*)d_in[11];
    const float* W3_st = (const float*)d_in[12], *b3_st = (const float*)d_in[13];
    const float* W1_wm = (const float*)d_in[14], *b1_wm = (const float*)d_in[15];
    const float* W2_wm = (const float*)d_in[16], *b2_wm = (const float*)d_in[17];
    const float* W3_wm = (const float*)d_in[18], *b3_wm = (const float*)d_in[19];
    const float* W1_ch = (const float*)d_in[20], *b1_ch = (const float*)d_in[21];
    const float* W2_ch = (const float*)d_in[22], *b2_ch = (const float*)d_in[23];
    const float* W3_ch = (const float*)d_in[24], *b3_ch = (const float*)d_in[25];
    float* out = (float*)d_out;

    zero_cnt_kernel<<<1, 32>>>();
    bucket_kernel<<<NROWS / 256, 256>>>(labels, out);
    prep_kernel<<<768, 256>>>(W1_sc, W1_st, W1_wm, W1_ch);

    const size_t gemm_smem = (size_t)GEMM_SMEM_FLOATS * sizeof(float);  // ~74 KB
    cudaFuncSetAttribute(gemm_kernel, cudaFuncAttributeMaxDynamicSharedMemorySize,
                         (int)gemm_smem);
    gemm_kernel<<<6 * (NROWS / BM), NT, gemm_smem>>>(x, b1_sc, b1_st, b1_wm, b1_ch);

    const size_t s2_smem = (size_t)S2_FLOATS * sizeof(float);  // ~83.5 KB
    cudaFuncSetAttribute(stage2_kernel, cudaFuncAttributeMaxDynamicSharedMemorySize,
                         (int)s2_smem);
    stage2_kernel<<<592, 256, s2_smem>>>(
        W2_sc, b2_sc, W3_sc, b3_sc,
        W2_st, b2_st, W3_st, b3_st,
        W2_wm, b2_wm, W3_wm, b3_wm,
        W2_ch, b2_ch, W3_ch, b3_ch,
        out);
}

// round 9
// speedup vs baseline: 1.5633x; 1.5633x over previous
#include <cuda_runtime.h>
#include <stdint.h>

#define NROWS 65536
#define KDIM  2048
#define BM 128
#define BK 32
#define NKT (KDIM / BK)   // 64
#define NT  256

// ---------------- device scratch ----------------
__device__ int g_cnt[4];
__device__ int g_perm[4][NROWS];          // 1 MB
__device__ float g_W1T[384 * KDIM];       // 3 MB: W1^T n-major [n][k], tf32-rounded
__device__ float g_W2T[20480];            // W2^T n-major [n][k] per expert, tf32-rounded

#define W1ROW_SC 0
#define W1ROW_ST 64
#define W1ROW_WM 128
#define W1ROW_CH 256
#define W2OFF_SC 0
#define W2OFF_ST 2048
#define W2OFF_WM 4096
#define W2OFF_CH 12288

// ---------------- helpers ----------------
__device__ __forceinline__ void cp16(uint32_t dst, const float* src) {
    asm volatile("cp.async.ca.shared.global [%0], [%1], 16;\n" :: "r"(dst), "l"(src));
}
__device__ __forceinline__ uint32_t f2tf(float x) {
    uint32_t u; asm("cvt.rna.tf32.f32 %0, %1;" : "=r"(u) : "f"(x)); return u;
}
#define LDSM_X4(R0, R1, R2, R3, ADDR) \
    asm volatile("ldmatrix.sync.aligned.m8n8.x4.shared.b16 {%0,%1,%2,%3}, [%4];" \
        : "=r"(R0), "=r"(R1), "=r"(R2), "=r"(R3) : "r"(ADDR))

// ---------------- prep: transpose + tf32-round W1, W2 ----------------
__global__ void prep_kernel(const float* __restrict__ W1_sc, const float* __restrict__ W1_st,
                            const float* __restrict__ W1_wm, const float* __restrict__ W1_ch,
                            const float* __restrict__ W2_sc, const float* __restrict__ W2_st,
                            const float* __restrict__ W2_wm, const float* __restrict__ W2_ch) {
    const int T = 384 * KDIM;
    for (int i = blockIdx.x * blockDim.x + threadIdx.x; i < T;
         i += gridDim.x * blockDim.x) {
        int n = i >> 11, k = i & 2047;
        float v;
        if (n < 64)        v = W1_sc[k * 64 + n];
        else if (n < 128)  v = W1_st[k * 64 + (n - 64)];
        else if (n < 256)  v = W1_wm[(size_t)k * 128 + (n - 128)];
        else               v = W1_ch[(size_t)k * 128 + (n - 256)];
        g_W1T[i] = __uint_as_float(f2tf(v));
    }
    for (int i = blockIdx.x * blockDim.x + threadIdx.x; i < 20480;
         i += gridDim.x * blockDim.x) {
        float v;
        if (i < 2048)       { int j = i;          v = W2_sc[(j & 63) * 32 + (j >> 6)];  }
        else if (i < 4096)  { int j = i - 2048;   v = W2_st[(j & 63) * 32 + (j >> 6)];  }
        else if (i < 12288) { int j = i - 4096;   v = W2_wm[(j & 127) * 64 + (j >> 7)]; }
        else                { int j = i - 12288;  v = W2_ch[(j & 127) * 64 + (j >> 7)]; }
        g_W2T[i] = __uint_as_float(f2tf(v));
    }
}

// ---------------- bucket kernels ----------------
__global__ void zero_cnt_kernel() {
    if (threadIdx.x < 4) g_cnt[threadIdx.x] = 0;
}
__global__ void bucket_kernel(const int* __restrict__ labels, float* __restrict__ out) {
    int r = blockIdx.x * blockDim.x + threadIdx.x;
    if (r >= NROWS) return;
    int lab = labels[r];
    bool valid = (lab >= 0) && (lab <= 3);
    if (!valid) { out[r] = 0.f; lab = -1; }
    int lane = threadIdx.x & 31;
#pragma unroll
    for (int l = 0; l < 4; l++) {
        unsigned mask = __ballot_sync(0xffffffffu, lab == l);
        if (lab == l) {
            int leader = __ffs(mask) - 1;
            int myrank = __popc(mask & ((1u << lane) - 1));
            int basep = 0;
            if (lane == leader) basep = atomicAdd(&g_cnt[l], __popc(mask));
            basep = __shfl_sync(mask, basep, leader);
            g_perm[l][basep + myrank] = r;
        }
    }
}

// max smem (H=128): A 3x4096 + B 3x4096 + W2T 8192 + tail 384 = 33152 floats
#define SMEM_FLOATS 33152

// ---------------- fused expert body (256 thr, 8 warps = 4m x 2n, LDSM frags) ----------------
template<int H>
__device__ __forceinline__ void expert_body(
    int e, int chunk, const float* __restrict__ X,
    const float* __restrict__ W1T,   // [H rows][2048], tf32
    const float* __restrict__ W2T,   // [H2 rows][H], tf32
    const float* __restrict__ b1, const float* __restrict__ b2,
    const float* __restrict__ W3, const float* __restrict__ b3,
    float* __restrict__ out, float* smem)
{
    constexpr int H2   = H / 2;
    constexpr int JB   = H / 16;     // layer-1 n8 blocks/warp
    constexpr int JP   = H / 32;     // layer-1 jpairs (x4 ldsm covers 2 j)
    constexpr int JB2  = H2 / 16;
    constexpr int JP2  = H2 / 32;
    constexpr int ABUF = 4096;       // floats per A stage (128x32)
    constexpr int BBUF = H * 32;     // floats per B stage (H rows x 32 k)
    constexpr int OFF_B    = 3 * ABUF;
    constexpr int OFF_W2   = OFF_B + 3 * BBUF;
    constexpr int OFF_TAIL = OFF_W2 + H * H2;

    int count = g_cnt[e];
    int base = chunk * BM;
    if (base >= count) return;
    const int* perm = g_perm[e];

    uint32_t sbase = (uint32_t)__cvta_generic_to_shared(smem);
    float* sW3   = smem + OFF_TAIL;
    float* sB2   = smem + OFF_TAIL + 64;
    float* sPart = smem + OFF_TAIL + 128;
    int*   sRow  = (int*)(smem + OFF_TAIL + 256);

    int tid = threadIdx.x, lane = tid & 31, warp = tid >> 5;
    int wm = warp & 3;        // 32 rows each
    int wn = warp >> 2;       // 0..1, H/2 cols each

    if (tid < BM) {
        int idx = base + tid;
        if (idx >= count) idx = count - 1;
        sRow[tid] = perm[idx];
    }
    if (tid < H2) { sW3[tid] = W3[tid]; sB2[tid] = b2[tid]; }
    __syncthreads();

    int rid[4];
#pragma unroll
    for (int it = 0; it < 4; it++) rid[it] = sRow[(tid + it * NT) >> 3];

    float acc[2][JB][4];
#pragma unroll
    for (int i = 0; i < 2; i++)
#pragma unroll
        for (int j = 0; j < JB; j++)
#pragma unroll
            for (int r = 0; r < 4; r++) acc[i][j][r] = 0.f;

    // tile layout: row-major, 128B rows (32 k x 4B), 16B chunk c swizzled c^(row&7)
    auto loadA = [&](int buf, int kt) {
        uint32_t dbase = sbase + buf * (ABUF * 4);
#pragma unroll
        for (int it = 0; it < 4; it++) {
            int slot = tid + it * NT;
            int r = slot >> 3, c = slot & 7;
            cp16(dbase + r * 128 + ((c ^ (r & 7)) << 4),
                 X + (size_t)rid[it] * KDIM + kt * BK + c * 4);
        }
    };
    auto loadB = [&](int buf, int kt) {
        uint32_t dbase = sbase + (OFF_B + buf * BBUF) * 4;
#pragma unroll
        for (int it = 0; it < (H * 8) / NT; it++) {
            int slot = tid + it * NT;
            int r = slot >> 3, c = slot & 7;       // r = n row, c = k quad
            cp16(dbase + r * 128 + ((c ^ (r & 7)) << 4),
                 W1T + (size_t)r * KDIM + kt * BK + c * 4);
        }
    };
    // W2T tile: H2 rows x H k -> rows of H*4 bytes, H/4 quads, swizzle low3
    auto loadW2 = [&]() {
        uint32_t dbase = sbase + OFF_W2 * 4;
        constexpr int CQ = H / 4;
#pragma unroll
        for (int it = 0; it < (H2 * CQ) / NT; it++) {
            int slot = tid + it * NT;
            int r = slot / CQ, c = slot % CQ;
            cp16(dbase + r * (H * 4) + ((c ^ (r & 7)) << 4),
                 W2T + (size_t)r * H + c * 4);
        }
    };

    loadA(0, 0); loadB(0, 0);
    asm volatile("cp.async.commit_group;\n");
    loadA(1, 1); loadB(1, 1);
    asm volatile("cp.async.commit_group;\n");

    // per-lane LDSM row components (layer 1)
    int a_row_in = ((lane >> 3) & 1) * 8 + (lane & 7);   // + wm*32 + i*16
    int a_kq_hi  = lane >> 4;                            // + ks*2
    int b_row_in = ((lane >> 4) & 1) * 8 + (lane & 7);   // + wn*(H/2) + jp*16
    int b_kq_hi  = (lane >> 3) & 1;                      // + ks*2

    for (int kt = 0; kt < NKT; kt++) {
        int buf = kt % 3;
        if (kt + 2 < NKT) {
            int nb = (kt + 2) % 3;
            loadA(nb, kt + 2);
            loadB(nb, kt + 2);
            asm volatile("cp.async.commit_group;\n");
            asm volatile("cp.async.wait_group 2;\n");
        } else if (kt + 1 < NKT) {
            loadW2();
            asm volatile("cp.async.commit_group;\n");
            asm volatile("cp.async.wait_group 2;\n");
        } else {
            asm volatile("cp.async.wait_group 1;\n");
        }
        __syncthreads();

        uint32_t Ab = sbase + buf * (ABUF * 4);
        uint32_t Bb = sbase + (OFF_B + buf * BBUF) * 4;

#pragma unroll
        for (int ks = 0; ks < 4; ks++) {
            uint32_t afr[2][4];
#pragma unroll
            for (int i = 0; i < 2; i++) {
                int row = wm * 32 + i * 16 + a_row_in;
                int kq  = ks * 2 + a_kq_hi;
                uint32_t ad = Ab + row * 128 + (((kq ^ (row & 7))) << 4);
                LDSM_X4(afr[i][0], afr[i][1], afr[i][2], afr[i][3], ad);
            }
#pragma unroll
            for (int i = 0; i < 2; i++)
#pragma unroll
                for (int r = 0; r < 4; r++)
                    afr[i][r] = f2tf(__uint_as_float(afr[i][r]));

            uint32_t bfr[JB][2];
#pragma unroll
            for (int jp = 0; jp < JP; jp++) {
                int n  = wn * (H / 2) + jp * 16 + b_row_in;
                int kq = ks * 2 + b_kq_hi;
                uint32_t bd = Bb + n * 128 + (((kq ^ (n & 7))) << 4);
                LDSM_X4(bfr[2 * jp][0], bfr[2 * jp][1],
                        bfr[2 * jp + 1][0], bfr[2 * jp + 1][1], bd);
            }
#pragma unroll
            for (int i = 0; i < 2; i++)
#pragma unroll
                for (int j = 0; j < JB; j++) {
                    asm volatile(
                        "mma.sync.aligned.m16n8k8.row.col.f32.tf32.tf32.f32 "
                        "{%0,%1,%2,%3}, {%4,%5,%6,%7}, {%8,%9}, {%0,%1,%2,%3};\n"
                        : "+f"(acc[i][j][0]), "+f"(acc[i][j][1]),
                          "+f"(acc[i][j][2]), "+f"(acc[i][j][3])
                        : "r"(afr[i][0]), "r"(afr[i][1]), "r"(afr[i][2]), "r"(afr[i][3]),
                          "r"(bfr[j][0]), "r"(bfr[j][1]));
                }
        }
        __syncthreads();
    }

    // ---- layer-1 epilogue: +b1, relu, tf32-round, h1 -> smem[0..BM*H) ----
    // h1 layout: row-major, rows of H*4 bytes, quad swizzle (colq ^ (row&7)) low3
#pragma unroll
    for (int i = 0; i < 2; i++) {
        int row0 = wm * 32 + i * 16 + (lane >> 2);
        int row1 = row0 + 8;
#pragma unroll
        for (int j = 0; j < JB; j++) {
            int col = wn * (H / 2) + j * 8 + 2 * (lane & 3);
            float bv0 = __ldg(b1 + col), bv1 = __ldg(b1 + col + 1);
            float2 v0, v1;
            v0.x = __uint_as_float(f2tf(fmaxf(acc[i][j][0] + bv0, 0.f)));
            v0.y = __uint_as_float(f2tf(fmaxf(acc[i][j][1] + bv1, 0.f)));
            v1.x = __uint_as_float(f2tf(fmaxf(acc[i][j][2] + bv0, 0.f)));
            v1.y = __uint_as_float(f2tf(fmaxf(acc[i][j][3] + bv1, 0.f)));
            int cq = col >> 2, cr = col & 3;
            *(float2*)((char*)smem + row0 * (H * 4) + ((cq ^ (row0 & 7)) << 4) + cr * 4) = v0;
            *(float2*)((char*)smem + row1 * (H * 4) + ((cq ^ (row1 & 7)) << 4) + cr * 4) = v1;
        }
    }
    asm volatile("cp.async.wait_group 0;\n");   // W2T landed
    __syncthreads();

    // ---- layer 2: acc2 = h1 @ W2T^T (LDSM + mma; operands pre-rounded) ----
    float acc2[2][JB2][4];
#pragma unroll
    for (int i = 0; i < 2; i++)
#pragma unroll
        for (int j = 0; j < JB2; j++)
#pragma unroll
            for (int r = 0; r < 4; r++) acc2[i][j][r] = 0.f;

    uint32_t W2b = sbase + OFF_W2 * 4;
#pragma unroll
    for (int ks = 0; ks < H / 8; ks++) {
        uint32_t afr[2][4];
#pragma unroll
        for (int i = 0; i < 2; i++) {
            int row = wm * 32 + i * 16 + a_row_in;
            int kq  = ks * 2 + a_kq_hi;
            uint32_t ad = sbase + row * (H * 4) + (((kq ^ (row & 7)) & (H / 4 - 1)) << 4)
                        + ((kq ^ (row & 7)) & ~(H / 4 - 1)) * 16;   // kq < H/4, swizzle low3 only
            // simpler: swizzle affects low 3 bits only; kq up to H/4-1
            ad = sbase + row * (H * 4) + ((kq ^ (row & 7)) << 4);
            LDSM_X4(afr[i][0], afr[i][1], afr[i][2], afr[i][3], ad);
        }
        uint32_t bfr[JB2][2];
#pragma unroll
        for (int jp = 0; jp < JP2; jp++) {
            int n  = wn * (H2 / 2) + jp * 16 + b_row_in;
            int kq = ks * 2 + b_kq_hi;
            uint32_t bd = W2b + n * (H * 4) + ((kq ^ (n & 7)) << 4);
            LDSM_X4(bfr[2 * jp][0], bfr[2 * jp][1],
                    bfr[2 * jp + 1][0], bfr[2 * jp + 1][1], bd);
        }
#pragma unroll
        for (int i = 0; i < 2; i++)
#pragma unroll
            for (int j = 0; j < JB2; j++) {
                asm volatile(
                    "mma.sync.aligned.m16n8k8.row.col.f32.tf32.tf32.f32 "
                    "{%0,%1,%2,%3}, {%4,%5,%6,%7}, {%8,%9}, {%0,%1,%2,%3};\n"
                    : "+f"(acc2[i][j][0]), "+f"(acc2[i][j][1]),
                      "+f"(acc2[i][j][2]), "+f"(acc2[i][j][3])
                    : "r"(afr[i][0]), "r"(afr[i][1]), "r"(afr[i][2]), "r"(afr[i][3]),
                      "r"(bfr[j][0]), "r"(bfr[j][1]));
            }
    }

    // ---- layer 3: +b2, relu, dot W3, reduce, +b3, scatter ----
    float p[4] = {0.f, 0.f, 0.f, 0.f};
#pragma unroll
    for (int i = 0; i < 2; i++)
#pragma unroll
        for (int j = 0; j < JB2; j++) {
            int col = wn * (H2 / 2) + j * 8 + 2 * (lane & 3);
            float w0 = sW3[col], w1 = sW3[col + 1];
            float c0 = sB2[col], c1 = sB2[col + 1];
            p[i * 2 + 0] += fmaxf(acc2[i][j][0] + c0, 0.f) * w0
                          + fmaxf(acc2[i][j][1] + c1, 0.f) * w1;
            p[i * 2 + 1] += fmaxf(acc2[i][j][2] + c0, 0.f) * w0
                          + fmaxf(acc2[i][j][3] + c1, 0.f) * w1;
        }
#pragma unroll
    for (int t = 0; t < 4; t++) {
        p[t] += __shfl_xor_sync(0xffffffffu, p[t], 1);
        p[t] += __shfl_xor_sync(0xffffffffu, p[t], 2);
    }
    if (wn == 0 && (lane & 3) == 0) {
#pragma unroll
        for (int i = 0; i < 2; i++)
#pragma unroll
            for (int hh = 0; hh < 2; hh++) {
                int m = wm * 32 + i * 16 + hh * 8 + (lane >> 2);
                sPart[m] = p[i * 2 + hh];
            }
    }
    __syncthreads();
    if (wn == 1 && (lane & 3) == 0) {
        float b3v = __ldg(b3);
#pragma unroll
        for (int i = 0; i < 2; i++)
#pragma unroll
            for (int hh = 0; hh < 2; hh++) {
                int m = wm * 32 + i * 16 + hh * 8 + (lane >> 2);
                if (base + m < count)
                    out[sRow[m]] = sPart[m] + p[i * 2 + hh] + b3v;
            }
    }
}

// ---------------- fused kernel ----------------
__global__ __launch_bounds__(NT) void fused_kernel(
    const float* __restrict__ X,
    const float* __restrict__ b1_sc, const float* __restrict__ b2_sc,
    const float* __restrict__ W3_sc, const float* __restrict__ b3_sc,
    const float* __restrict__ b1_st, const float* __restrict__ b2_st,
    const float* __restrict__ W3_st, const float* __restrict__ b3_st,
    const float* __restrict__ b1_wm, const float* __restrict__ b2_wm,
    const float* __restrict__ W3_wm, const float* __restrict__ b3_wm,
    const float* __restrict__ b1_ch, const float* __restrict__ b2_ch,
    const float* __restrict__ W3_ch, const float* __restrict__ b3_ch,
    float* __restrict__ out)
{
    extern __shared__ float smem[];
    int e = blockIdx.x & 3;
    int chunk = blockIdx.x >> 2;
    if (e == 0)
        expert_body<64>(0, chunk, X, g_W1T + (size_t)W1ROW_SC * KDIM, g_W2T + W2OFF_SC,
                        b1_sc, b2_sc, W3_sc, b3_sc, out, smem);
    else if (e == 1)
        expert_body<64>(1, chunk, X, g_W1T + (size_t)W1ROW_ST * KDIM, g_W2T + W2OFF_ST,
                        b1_st, b2_st, W3_st, b3_st, out, smem);
    else if (e == 2)
        expert_body<128>(2, chunk, X, g_W1T + (size_t)W1ROW_WM * KDIM, g_W2T + W2OFF_WM,
                         b1_wm, b2_wm, W3_wm, b3_wm, out, smem);
    else
        expert_body<128>(3, chunk, X, g_W1T + (size_t)W1ROW_CH * KDIM, g_W2T + W2OFF_CH,
                         b1_ch, b2_ch, W3_ch, b3_ch, out, smem);
}

// ---------------- launch ----------------
extern "C" void kernel_launch(void* const* d_in, const int* in_sizes, int n_in,
                              void* d_out, int out_size) {
    const float* x      = (const float*)d_in[0];
    const int*   labels = (const int*)d_in[1];
    const float* W1_sc = (const float*)d_in[2],  *b1_sc = (const float*)d_in[3];
    const float* W2_sc = (const float*)d_in[4],  *b2_sc = (const float*)d_in[5];
    const float* W3_sc = (const float*)d_in[6],  *b3_sc = (const float*)d_in[7];
    const float* W1_st = (const float*)d_in[8],  *b1_st = (const float*)d_in[9];
    const float* W2_st = (const float*)d_in[10], *b2_st = (const float*)d_in[11];
    const float* W3_st = (const float*)d_in[12], *b3_st = (const float*)d_in[13];
    const float* W1_wm = (const float*)d_in[14], *b1_wm = (const float*)d_in[15];
    const float* W2_wm = (const float*)d_in[16], *b2_wm = (const float*)d_in[17];
    const float* W3_wm = (const float*)d_in[18], *b3_wm = (const float*)d_in[19];
    const float* W1_ch = (const float*)d_in[20], *b1_ch = (const float*)d_in[21];
    const float* W2_ch = (const float*)d_in[22], *b2_ch = (const float*)d_in[23];
    const float* W3_ch = (const float*)d_in[24], *b3_ch = (const float*)d_in[25];
    float* out = (float*)d_out;

    zero_cnt_kernel<<<1, 32>>>();
    bucket_kernel<<<NROWS / 256, 256>>>(labels, out);
    prep_kernel<<<768, 256>>>(W1_sc, W1_st, W1_wm, W1_ch,
                              W2_sc, W2_st, W2_wm, W2_ch);

    const size_t smem_bytes = (size_t)SMEM_FLOATS * sizeof(float);  // 132,608 B
    cudaFuncSetAttribute(fused_kernel, cudaFuncAttributeMaxDynamicSharedMemorySize,
                         (int)smem_bytes);

    fused_kernel<<<4 * (NROWS / BM), NT, smem_bytes>>>(x,
        b1_sc, b2_sc, W3_sc, b3_sc,
        b1_st, b2_st, W3_st, b3_st,
        b1_wm, b2_wm, W3_wm, b3_wm,
        b1_ch, b2_ch, W3_ch, b3_ch,
        out);
}